// round 1
// baseline (speedup 1.0000x reference)
#include <cuda_runtime.h>
#include <math.h>

#define Hd 1024
#define Sd 2048
#define Bd 16
#define Ad 8

#define BM 128
#define BN 128
#define BK 8
#define TM 8
#define TN 8

// scratch (allocation-free rule: __device__ globals)
__device__ float g_cvec[Bd * Hd];     // asp@W2 + bias, per batch
__device__ float g_scores[Bd * Sd];
__device__ float g_weights[Bd * Sd];

// ---------------------------------------------------------------------------
// Kernel 1: cvec[b][h] = bias[h] + sum_k mean_a(aspect[b,a,k]) * W[H+k][h]
// grid (16, 4) x 256 threads; each thread owns one h.
// ---------------------------------------------------------------------------
__global__ void cvec_kernel(const float* __restrict__ aspect,
                            const float* __restrict__ W,
                            const float* __restrict__ bias) {
    __shared__ float asp[Hd];
    int b = blockIdx.x;
    int tid = threadIdx.x;

    for (int k = tid; k < Hd; k += 256) {
        float s = 0.f;
        #pragma unroll
        for (int a = 0; a < Ad; ++a)
            s += aspect[(size_t)(b * Ad + a) * Hd + k];
        asp[k] = s * (1.0f / Ad);
    }
    __syncthreads();

    int h = blockIdx.y * 256 + tid;
    float acc = bias[h];
    const float* Wp = W + (size_t)Hd * Hd + h;  // W2 column h: W[(H+k)*H + h]
    #pragma unroll 8
    for (int k = 0; k < Hd; ++k)
        acc = fmaf(asp[k], Wp[(size_t)k * Hd], acc);
    g_cvec[b * Hd + h] = acc;
}

// ---------------------------------------------------------------------------
// Kernel 2: fused GEMM + tanh + v-dot.
// scores[m] = sum_n v[n] * tanh( (X @ W1)[m][n] + cvec[b][n] )
// One CTA per 128 rows; loops over all 8 N-tiles so no atomics needed.
// ---------------------------------------------------------------------------
__global__ void __launch_bounds__(256, 2)
gemm_score_kernel(const float* __restrict__ X,
                  const float* __restrict__ W,
                  const float* __restrict__ v) {
    __shared__ float Xs[BK][BM + 4];   // +4 pad: conflict-free transpose store
    __shared__ float Ws[BK][BN];
    __shared__ float sred[BM][17];     // pad 17: conflict-free row reduce

    int m0 = blockIdx.x * BM;
    int b  = m0 >> 11;                 // 2048 rows per batch, BM divides 2048
    int tid = threadIdx.x;
    int tx = tid & 15, ty = tid >> 4;

    // X tile load mapping: 128 rows x 8 k, one float4 per thread
    int xrow = tid >> 1;
    int xk   = (tid & 1) * 4;
    // W tile load mapping: 8 k x 128 n, one float4 per thread
    int wk = tid >> 5;
    int wn = (tid & 31) * 4;

    float sc[TM];
    #pragma unroll
    for (int i = 0; i < TM; i++) sc[i] = 0.f;

    for (int nt = 0; nt < Hd / BN; ++nt) {
        float acc[TM][TN];
        #pragma unroll
        for (int i = 0; i < TM; i++)
            #pragma unroll
            for (int j = 0; j < TN; j++) acc[i][j] = 0.f;

        const float* Wp = W + nt * BN;

        for (int k0 = 0; k0 < Hd; k0 += BK) {
            float4 xv = *(const float4*)(X + (size_t)(m0 + xrow) * Hd + k0 + xk);
            float4 wv = *(const float4*)(Wp + (size_t)(k0 + wk) * Hd + wn);
            Xs[xk + 0][xrow] = xv.x;
            Xs[xk + 1][xrow] = xv.y;
            Xs[xk + 2][xrow] = xv.z;
            Xs[xk + 3][xrow] = xv.w;
            *(float4*)&Ws[wk][wn] = wv;
            __syncthreads();

            #pragma unroll
            for (int k = 0; k < BK; k++) {
                float4 a0 = *(const float4*)&Xs[k][ty * TM];
                float4 a1 = *(const float4*)&Xs[k][ty * TM + 4];
                float4 b0 = *(const float4*)&Ws[k][tx * TN];
                float4 b1 = *(const float4*)&Ws[k][tx * TN + 4];
                float av[8] = {a0.x, a0.y, a0.z, a0.w, a1.x, a1.y, a1.z, a1.w};
                float bv[8] = {b0.x, b0.y, b0.z, b0.w, b1.x, b1.y, b1.z, b1.w};
                #pragma unroll
                for (int i = 0; i < TM; i++)
                    #pragma unroll
                    for (int j = 0; j < TN; j++)
                        acc[i][j] = fmaf(av[i], bv[j], acc[i][j]);
            }
            __syncthreads();
        }

        // epilogue for this N tile: tanh + v-dot, accumulate into row partials
        float cv[TN], vv[TN];
        #pragma unroll
        for (int j = 0; j < TN; j++) {
            int n = nt * BN + tx * TN + j;
            cv[j] = g_cvec[b * Hd + n];
            vv[j] = v[n];
        }
        #pragma unroll
        for (int i = 0; i < TM; i++) {
            float p = 0.f;
            #pragma unroll
            for (int j = 0; j < TN; j++)
                p += vv[j] * tanhf(acc[i][j] + cv[j]);
            sc[i] += p;
        }
    }

    // cross-thread reduce: 16 tx partials per row
    #pragma unroll
    for (int i = 0; i < TM; i++) sred[ty * TM + i][tx] = sc[i];
    __syncthreads();
    if (tid < BM) {
        float s = 0.f;
        #pragma unroll
        for (int t = 0; t < 16; t++) s += sred[tid][t];
        g_scores[m0 + tid] = s;
    }
}

// ---------------------------------------------------------------------------
// Kernel 3: softmax over S per batch. 16 CTAs x 256 threads.
// ---------------------------------------------------------------------------
__global__ void softmax_kernel() {
    int b = blockIdx.x, tid = threadIdx.x;
    __shared__ float red[256];

    float m = -1e30f;
    for (int s = tid; s < Sd; s += 256)
        m = fmaxf(m, g_scores[b * Sd + s]);
    red[tid] = m;
    __syncthreads();
    for (int o = 128; o > 0; o >>= 1) {
        if (tid < o) red[tid] = fmaxf(red[tid], red[tid + o]);
        __syncthreads();
    }
    float mx = red[0];
    __syncthreads();

    float sum = 0.f;
    for (int s = tid; s < Sd; s += 256) {
        float e = expf(g_scores[b * Sd + s] - mx);
        g_weights[b * Sd + s] = e;
        sum += e;
    }
    red[tid] = sum;
    __syncthreads();
    for (int o = 128; o > 0; o >>= 1) {
        if (tid < o) red[tid] += red[tid + o];
        __syncthreads();
    }
    float inv = 1.0f / red[0];
    for (int s = tid; s < Sd; s += 256)
        g_weights[b * Sd + s] *= inv;
}

// ---------------------------------------------------------------------------
// Kernel 4: out = token * (1 + weights[row]); float4 vectorized.
// ---------------------------------------------------------------------------
__global__ void scale_kernel(const float* __restrict__ X, float* __restrict__ out,
                             int total4) {
    int idx = blockIdx.x * blockDim.x + threadIdx.x;
    int stride = gridDim.x * blockDim.x;
    for (int i = idx; i < total4; i += stride) {
        float w = 1.0f + g_weights[i >> 8];   // 256 float4 per row of H=1024
        float4 t = ((const float4*)X)[i];
        t.x *= w; t.y *= w; t.z *= w; t.w *= w;
        ((float4*)out)[i] = t;
    }
}

// ---------------------------------------------------------------------------
extern "C" void kernel_launch(void* const* d_in, const int* in_sizes, int n_in,
                              void* d_out, int out_size) {
    const float* tok  = (const float*)d_in[0];  // [16,2048,1024]
    const float* asp  = (const float*)d_in[1];  // [16,8,1024]
    const float* W    = (const float*)d_in[2];  // [2048,1024]
    const float* bias = (const float*)d_in[3];  // [1024]
    const float* v    = (const float*)d_in[4];  // [1024]
    float* out = (float*)d_out;                 // [16,2048,1024]

    cvec_kernel<<<dim3(Bd, Hd / 256), 256>>>(asp, W, bias);
    gemm_score_kernel<<<(Bd * Sd) / BM, 256>>>(tok, W, v);
    softmax_kernel<<<Bd, 256>>>();
    scale_kernel<<<8192, 256>>>(tok, out, (Bd * Sd * Hd) / 4);
}

// round 3
// speedup vs baseline: 4.6696x; 4.6696x over previous
#include <cuda_runtime.h>
#include <cuda_bf16.h>
#include <stdint.h>
#include <math.h>

#define Hd 1024
#define Sd 2048
#define Bd 16
#define Ad 8

#define BM 128
#define BN 128
#define BKg 32
#define STG 4
#define LDT 80                      // padded row pitch in BYTES (40 bf16)
#define A_BYTES (BM * LDT)          // 10240
#define SB_OFF  A_BYTES
#define STAGE_BYTES (2 * A_BYTES)   // 20480
#define SM_V    (STG * STAGE_BYTES)         // 81920
#define SM_C    (SM_V + 4096)               // 86016
#define SM_SRED (SM_C + 4096)               // 90112
#define SMEM_TOTAL (SM_SRED + 1024)         // 91136

// ---------------------------------------------------------------------------
// device scratch (allocation-free rule)
// ---------------------------------------------------------------------------
__device__ __nv_bfloat16 g_Xbf[(size_t)Bd * Sd * Hd];  // 64 MB
__device__ __nv_bfloat16 g_Wt[(size_t)Hd * Hd];        // W1^T: [N][K], K contiguous
__device__ float g_cvec[Bd * Hd];
__device__ float g_scores[Bd * Sd];
__device__ float g_weights[Bd * Sd];

// ---------------------------------------------------------------------------
// helpers (all family-portable: sm_80+ ISA only)
// ---------------------------------------------------------------------------
__device__ __forceinline__ uint32_t smem_u32(const void* p) {
    uint32_t a;
    asm("{ .reg .u64 t; cvta.to.shared.u64 t, %1; cvt.u32.u64 %0, t; }" : "=r"(a) : "l"(p));
    return a;
}
__device__ __forceinline__ void cpa16(uint32_t dst, const void* src) {
    asm volatile("cp.async.cg.shared.global [%0], [%1], 16;" :: "r"(dst), "l"(src));
}
__device__ __forceinline__ void cpa_commit() {
    asm volatile("cp.async.commit_group;" ::: "memory");
}
#define CPA_WAIT2() asm volatile("cp.async.wait_group 2;" ::: "memory")
#define LDSM4(r, addr)                                                        \
    asm volatile("ldmatrix.sync.aligned.m8n8.x4.shared.b16 {%0,%1,%2,%3}, [%4];" \
        : "=r"((r)[0]), "=r"((r)[1]), "=r"((r)[2]), "=r"((r)[3]) : "r"(addr))
__device__ __forceinline__ void mma16816(float* d, const uint32_t* a,
                                         uint32_t b0, uint32_t b1) {
    asm volatile(
        "mma.sync.aligned.m16n8k16.row.col.f32.bf16.bf16.f32 "
        "{%0,%1,%2,%3}, {%4,%5,%6,%7}, {%8,%9}, {%0,%1,%2,%3};"
        : "+f"(d[0]), "+f"(d[1]), "+f"(d[2]), "+f"(d[3])
        : "r"(a[0]), "r"(a[1]), "r"(a[2]), "r"(a[3]), "r"(b0), "r"(b1));
}
__device__ __forceinline__ float fast_tanh(float x) {
    float y;
    asm("tanh.approx.f32 %0, %1;" : "=f"(y) : "f"(x));
    return y;
}

// ---------------------------------------------------------------------------
// Prep kernels
// ---------------------------------------------------------------------------
__global__ void convert_x(const float4* __restrict__ X4) {
    int n4 = Bd * Sd * Hd / 4;
    for (int i = blockIdx.x * blockDim.x + threadIdx.x; i < n4; i += gridDim.x * blockDim.x) {
        float4 v = X4[i];
        __nv_bfloat162 lo = __floats2bfloat162_rn(v.x, v.y);
        __nv_bfloat162 hi = __floats2bfloat162_rn(v.z, v.w);
        uint2 pk;
        pk.x = *reinterpret_cast<uint32_t*>(&lo);
        pk.y = *reinterpret_cast<uint32_t*>(&hi);
        reinterpret_cast<uint2*>(g_Xbf)[i] = pk;
    }
}

__global__ void transpose_w(const float* __restrict__ W) {
    __shared__ float t[32][33];
    int tx = threadIdx.x, ty = threadIdx.y;       // 32 x 8
    int n0 = blockIdx.x * 32, k0 = blockIdx.y * 32;
    #pragma unroll
    for (int i = 0; i < 32; i += 8)
        t[ty + i][tx] = W[(size_t)(k0 + ty + i) * Hd + n0 + tx];
    __syncthreads();
    #pragma unroll
    for (int i = 0; i < 32; i += 8)
        g_Wt[(size_t)(n0 + ty + i) * Hd + k0 + tx] = __float2bfloat16(t[tx][ty + i]);
}

__global__ void cvec_kernel(const float* __restrict__ aspect,
                            const float* __restrict__ W,
                            const float* __restrict__ bias) {
    __shared__ float asp[Hd];
    int b = blockIdx.x;
    int tid = threadIdx.x;
    for (int k = tid; k < Hd; k += 256) {
        float s = 0.f;
        #pragma unroll
        for (int a = 0; a < Ad; ++a)
            s += aspect[(size_t)(b * Ad + a) * Hd + k];
        asp[k] = s * (1.0f / Ad);
    }
    __syncthreads();
    int h = blockIdx.y * 256 + tid;
    float acc = bias[h];
    const float* Wp = W + (size_t)Hd * Hd + h;
    #pragma unroll 8
    for (int k = 0; k < Hd; ++k)
        acc = fmaf(asp[k], Wp[(size_t)k * Hd], acc);
    g_cvec[b * Hd + h] = acc;
}

// ---------------------------------------------------------------------------
// Fused mma.sync GEMM + tanh + v-dot -> scores
// 256 threads = 8 warps, warp grid 4(M) x 2(N), warp tile 32x64.
// CTA computes 128 rows x full N=1024 (8 N-tiles of 128), K=1024 in BK=32.
// ---------------------------------------------------------------------------
__global__ void __launch_bounds__(256)
gemm_score_mma(const float* __restrict__ v) {
    extern __shared__ char smem[];
    uint32_t sb = smem_u32(smem);
    float* v_s  = reinterpret_cast<float*>(smem + SM_V);
    float* c_s  = reinterpret_cast<float*>(smem + SM_C);
    float* sred = reinterpret_cast<float*>(smem + SM_SRED);

    int tid = threadIdx.x, lane = tid & 31, wid = tid >> 5;
    int warpM = wid & 3, warpN = wid >> 2;
    int m0 = blockIdx.x * BM;
    int b = m0 >> 11;

    for (int i = tid; i < Hd; i += 256) {
        v_s[i] = v[i];
        c_s[i] = g_cvec[b * Hd + i];
    }

    // ldmatrix per-thread offsets (byte offsets within a stage)
    uint32_t aoff[2], boff[4];
    #pragma unroll
    for (int mt = 0; mt < 2; ++mt) {
        int r = warpM * 32 + mt * 16 + ((lane >> 3) & 1) * 8 + (lane & 7);
        aoff[mt] = r * LDT + (lane >> 4) * 16;
    }
    #pragma unroll
    for (int jp = 0; jp < 4; ++jp) {
        int n = warpN * 64 + (jp * 2 + (lane >> 4)) * 8 + (lane & 7);
        boff[jp] = SB_OFF + n * LDT + ((lane >> 3) & 1) * 16;
    }

    const __nv_bfloat16* Ag = g_Xbf + (size_t)m0 * Hd;
    const __nv_bfloat16* Bg = g_Wt;

    // cp.async mapping: 512 16B chunks per tile, 2 per thread per tile
    int lr  = tid >> 2;            // rows 0..63
    int lc  = (tid & 3) * 16;      // byte col within row (data = 64B)
    int lck = (tid & 3) * 8;       // element col

    float acc[2][8][4];
    #pragma unroll
    for (int mt = 0; mt < 2; ++mt)
        #pragma unroll
        for (int j = 0; j < 8; ++j)
            #pragma unroll
            for (int e = 0; e < 4; ++e) acc[mt][j][e] = 0.f;
    float p[4] = {0.f, 0.f, 0.f, 0.f};

    const int G = 8 * 32;   // 8 N-tiles x 32 K-chunks

    // prologue: preload 3 stages
    #pragma unroll
    for (int q = 0; q < STG - 1; ++q) {
        int n0 = (q >> 5) * BN, k0 = (q & 31) * BKg;
        uint32_t base = sb + (q & 3) * STAGE_BYTES;
        cpa16(base + lr * LDT + lc,            Ag + (size_t)lr * Hd + k0 + lck);
        cpa16(base + (lr + 64) * LDT + lc,     Ag + (size_t)(lr + 64) * Hd + k0 + lck);
        cpa16(base + SB_OFF + lr * LDT + lc,        Bg + (size_t)(n0 + lr) * Hd + k0 + lck);
        cpa16(base + SB_OFF + (lr + 64) * LDT + lc, Bg + (size_t)(n0 + lr + 64) * Hd + k0 + lck);
        cpa_commit();
    }

    for (int g = 0; g < G; ++g) {
        CPA_WAIT2();
        __syncthreads();

        int q = g + STG - 1;
        if (q < G) {
            int n0 = (q >> 5) * BN, k0 = (q & 31) * BKg;
            uint32_t base = sb + (q & 3) * STAGE_BYTES;
            cpa16(base + lr * LDT + lc,            Ag + (size_t)lr * Hd + k0 + lck);
            cpa16(base + (lr + 64) * LDT + lc,     Ag + (size_t)(lr + 64) * Hd + k0 + lck);
            cpa16(base + SB_OFF + lr * LDT + lc,        Bg + (size_t)(n0 + lr) * Hd + k0 + lck);
            cpa16(base + SB_OFF + (lr + 64) * LDT + lc, Bg + (size_t)(n0 + lr + 64) * Hd + k0 + lck);
            cpa_commit();
        }

        uint32_t ab = sb + (g & 3) * STAGE_BYTES;
        #pragma unroll
        for (int ks = 0; ks < 2; ++ks) {
            uint32_t a[2][4], bb[4][4];
            LDSM4(a[0], ab + aoff[0] + ks * 32);
            LDSM4(a[1], ab + aoff[1] + ks * 32);
            #pragma unroll
            for (int jp = 0; jp < 4; ++jp)
                LDSM4(bb[jp], ab + boff[jp] + ks * 32);
            #pragma unroll
            for (int mt = 0; mt < 2; ++mt)
                #pragma unroll
                for (int j = 0; j < 8; ++j)
                    mma16816(acc[mt][j], a[mt], bb[j >> 1][(j & 1) * 2],
                             bb[j >> 1][(j & 1) * 2 + 1]);
        }

        if ((g & 31) == 31) {
            // finished K for N-tile nt: tanh + v-dot in registers
            int nt = g >> 5;
            int nb = nt * BN + warpN * 64 + (lane & 3) * 2;
            #pragma unroll
            for (int mt = 0; mt < 2; ++mt)
                #pragma unroll
                for (int j = 0; j < 8; ++j) {
                    int n0e = nb + j * 8;
                    #pragma unroll
                    for (int e = 0; e < 4; ++e) {
                        int n = n0e + (e & 1);
                        float x = acc[mt][j][e] + c_s[n];
                        p[mt * 2 + (e >> 1)] += v_s[n] * fast_tanh(x);
                        acc[mt][j][e] = 0.f;
                    }
                }
        }
    }

    // reduce p over the 4 lanes sharing a row
    #pragma unroll
    for (int i = 0; i < 4; ++i) {
        p[i] += __shfl_xor_sync(0xFFFFFFFFu, p[i], 1);
        p[i] += __shfl_xor_sync(0xFFFFFFFFu, p[i], 2);
    }
    if ((lane & 3) == 0) {
        #pragma unroll
        for (int mt = 0; mt < 2; ++mt)
            #pragma unroll
            for (int rh = 0; rh < 2; ++rh) {
                int row = warpM * 32 + mt * 16 + (lane >> 2) + rh * 8;
                sred[row * 2 + warpN] = p[mt * 2 + rh];
            }
    }
    __syncthreads();
    if (tid < BM)
        g_scores[m0 + tid] = sred[tid * 2] + sred[tid * 2 + 1];
}

// ---------------------------------------------------------------------------
// softmax + scale
// ---------------------------------------------------------------------------
__global__ void softmax_kernel() {
    int b = blockIdx.x, tid = threadIdx.x;
    __shared__ float red[256];
    float m = -1e30f;
    for (int s = tid; s < Sd; s += 256)
        m = fmaxf(m, g_scores[b * Sd + s]);
    red[tid] = m;
    __syncthreads();
    for (int o = 128; o > 0; o >>= 1) {
        if (tid < o) red[tid] = fmaxf(red[tid], red[tid + o]);
        __syncthreads();
    }
    float mx = red[0];
    __syncthreads();
    float sum = 0.f;
    for (int s = tid; s < Sd; s += 256) {
        float e = expf(g_scores[b * Sd + s] - mx);
        g_weights[b * Sd + s] = e;
        sum += e;
    }
    red[tid] = sum;
    __syncthreads();
    for (int o = 128; o > 0; o >>= 1) {
        if (tid < o) red[tid] += red[tid + o];
        __syncthreads();
    }
    float inv = 1.0f / red[0];
    for (int s = tid; s < Sd; s += 256)
        g_weights[b * Sd + s] *= inv;
}

__global__ void scale_kernel(const float* __restrict__ X, float* __restrict__ out,
                             int total4) {
    int idx = blockIdx.x * blockDim.x + threadIdx.x;
    int stride = gridDim.x * blockDim.x;
    for (int i = idx; i < total4; i += stride) {
        float w = 1.0f + g_weights[i >> 8];
        float4 t = ((const float4*)X)[i];
        t.x *= w; t.y *= w; t.z *= w; t.w *= w;
        ((float4*)out)[i] = t;
    }
}

// ---------------------------------------------------------------------------
extern "C" void kernel_launch(void* const* d_in, const int* in_sizes, int n_in,
                              void* d_out, int out_size) {
    const float* tok  = (const float*)d_in[0];
    const float* asp  = (const float*)d_in[1];
    const float* W    = (const float*)d_in[2];
    const float* bias = (const float*)d_in[3];
    const float* v    = (const float*)d_in[4];
    float* out = (float*)d_out;

    cudaFuncSetAttribute(gemm_score_mma, cudaFuncAttributeMaxDynamicSharedMemorySize,
                         SMEM_TOTAL);

    convert_x<<<4096, 256>>>((const float4*)tok);
    transpose_w<<<dim3(32, 32), dim3(32, 8)>>>(W);
    cvec_kernel<<<dim3(Bd, Hd / 256), 256>>>(asp, W, bias);
    gemm_score_mma<<<(Bd * Sd) / BM, 256, SMEM_TOTAL>>>(v);
    softmax_kernel<<<Bd, 256>>>();
    scale_kernel<<<8192, 256>>>(tok, out, (Bd * Sd * Hd) / 4);
}

// round 5
// speedup vs baseline: 4.7653x; 1.0205x over previous
#include <cuda_runtime.h>
#include <cuda_bf16.h>
#include <stdint.h>
#include <math.h>

#define Hd 1024
#define Sd 2048
#define Bd 16
#define Ad 8

#define BM 128
#define BN 128
#define BKg 32
#define STG 4
#define LDT 80                      // padded row pitch in BYTES (40 bf16)
#define A_BYTES (BM * LDT)          // 10240
#define SB_OFF  A_BYTES
#define STAGE_BYTES (2 * A_BYTES)   // 20480
#define SM_V    (STG * STAGE_BYTES)         // 81920
#define SM_C    (SM_V + 4096)               // 86016
#define SM_SRED (SM_C + 4096)               // 90112
#define SMEM_TOTAL (SM_SRED + 1024)         // 91136

// ---------------------------------------------------------------------------
__device__ __nv_bfloat16 g_Xbf[(size_t)Bd * Sd * Hd];  // 64 MB
__device__ __nv_bfloat16 g_Wt[(size_t)Hd * Hd];        // W1^T: [N][K], K contiguous
__device__ float g_cvec[Bd * Hd];
__device__ float g_scores[Bd * Sd];
__device__ float g_weights[Bd * Sd];

// ---------------------------------------------------------------------------
__device__ __forceinline__ uint32_t smem_u32(const void* p) {
    uint32_t a;
    asm("{ .reg .u64 t; cvta.to.shared.u64 t, %1; cvt.u32.u64 %0, t; }" : "=r"(a) : "l"(p));
    return a;
}
__device__ __forceinline__ void cpa16(uint32_t dst, const void* src) {
    asm volatile("cp.async.cg.shared.global [%0], [%1], 16;" :: "r"(dst), "l"(src));
}
__device__ __forceinline__ void cpa_commit() {
    asm volatile("cp.async.commit_group;" ::: "memory");
}
#define CPA_WAIT2() asm volatile("cp.async.wait_group 2;" ::: "memory")
#define LDSM4(r, addr)                                                        \
    asm volatile("ldmatrix.sync.aligned.m8n8.x4.shared.b16 {%0,%1,%2,%3}, [%4];" \
        : "=r"((r)[0]), "=r"((r)[1]), "=r"((r)[2]), "=r"((r)[3]) : "r"(addr))
__device__ __forceinline__ void mma16816(float* d, const uint32_t* a,
                                         uint32_t b0, uint32_t b1) {
    asm volatile(
        "mma.sync.aligned.m16n8k16.row.col.f32.bf16.bf16.f32 "
        "{%0,%1,%2,%3}, {%4,%5,%6,%7}, {%8,%9}, {%0,%1,%2,%3};"
        : "+f"(d[0]), "+f"(d[1]), "+f"(d[2]), "+f"(d[3])
        : "r"(a[0]), "r"(a[1]), "r"(a[2]), "r"(a[3]), "r"(b0), "r"(b1));
}
__device__ __forceinline__ float fast_tanh(float x) {
    float y;
    asm("tanh.approx.f32 %0, %1;" : "=f"(y) : "f"(x));
    return y;
}

// ---------------------------------------------------------------------------
__global__ void convert_x(const float4* __restrict__ X4) {
    int n4 = Bd * Sd * Hd / 4;
    for (int i = blockIdx.x * blockDim.x + threadIdx.x; i < n4; i += gridDim.x * blockDim.x) {
        float4 v = X4[i];
        __nv_bfloat162 lo = __floats2bfloat162_rn(v.x, v.y);
        __nv_bfloat162 hi = __floats2bfloat162_rn(v.z, v.w);
        uint2 pk;
        pk.x = *reinterpret_cast<uint32_t*>(&lo);
        pk.y = *reinterpret_cast<uint32_t*>(&hi);
        reinterpret_cast<uint2*>(g_Xbf)[i] = pk;
    }
}

__global__ void transpose_w(const float* __restrict__ W) {
    __shared__ float t[32][33];
    int tx = threadIdx.x, ty = threadIdx.y;       // 32 x 8
    int n0 = blockIdx.x * 32, k0 = blockIdx.y * 32;
    #pragma unroll
    for (int i = 0; i < 32; i += 8)
        t[ty + i][tx] = W[(size_t)(k0 + ty + i) * Hd + n0 + tx];
    __syncthreads();
    #pragma unroll
    for (int i = 0; i < 32; i += 8)
        g_Wt[(size_t)(n0 + ty + i) * Hd + k0 + tx] = __float2bfloat16(t[tx][ty + i]);
}

__global__ void cvec_kernel(const float* __restrict__ aspect,
                            const float* __restrict__ W,
                            const float* __restrict__ bias) {
    __shared__ float asp[Hd];
    int b = blockIdx.x;
    int tid = threadIdx.x;
    for (int k = tid; k < Hd; k += 256) {
        float s = 0.f;
        #pragma unroll
        for (int a = 0; a < Ad; ++a)
            s += aspect[(size_t)(b * Ad + a) * Hd + k];
        asp[k] = s * (1.0f / Ad);
    }
    __syncthreads();
    int h = blockIdx.y * 256 + tid;
    float acc = bias[h];
    const float* Wp = W + (size_t)Hd * Hd + h;
    #pragma unroll 8
    for (int k = 0; k < Hd; ++k)
        acc = fmaf(asp[k], Wp[(size_t)k * Hd], acc);
    g_cvec[b * Hd + h] = acc;
}

// ---------------------------------------------------------------------------
// Fused mma.sync GEMM + tanh + v-dot -> scores
// 8 warps, warp grid 4(M) x 2(N), warp tile 32x64; 8 N-tiles, K in BK=32.
// Pipeline per iter g: wait(group g) -> barrier -> issue group g+3 -> compute.
// ---------------------------------------------------------------------------
__global__ void __launch_bounds__(256, 2)
gemm_score_mma(const float* __restrict__ v) {
    extern __shared__ char smem[];
    uint32_t sb = smem_u32(smem);
    float* v_s  = reinterpret_cast<float*>(smem + SM_V);
    float* c_s  = reinterpret_cast<float*>(smem + SM_C);
    float* sred = reinterpret_cast<float*>(smem + SM_SRED);

    int tid = threadIdx.x, lane = tid & 31, wid = tid >> 5;
    int warpM = wid & 3, warpN = wid >> 2;
    int m0 = blockIdx.x * BM;
    int b = m0 >> 11;

    for (int i = tid; i < Hd; i += 256) {
        v_s[i] = v[i];
        c_s[i] = g_cvec[b * Hd + i];
    }

    uint32_t aoff[2], boff[4];
    #pragma unroll
    for (int mt = 0; mt < 2; ++mt) {
        int r = warpM * 32 + mt * 16 + ((lane >> 3) & 1) * 8 + (lane & 7);
        aoff[mt] = r * LDT + (lane >> 4) * 16;
    }
    #pragma unroll
    for (int jp = 0; jp < 4; ++jp) {
        int n = warpN * 64 + (jp * 2 + (lane >> 4)) * 8 + (lane & 7);
        boff[jp] = SB_OFF + n * LDT + ((lane >> 3) & 1) * 16;
    }

    const __nv_bfloat16* Ag = g_Xbf + (size_t)m0 * Hd;
    const __nv_bfloat16* Bg = g_Wt;

    int lr  = tid >> 2;
    int lc  = (tid & 3) * 16;
    int lck = (tid & 3) * 8;

    float acc[2][8][4];
    #pragma unroll
    for (int mt = 0; mt < 2; ++mt)
        #pragma unroll
        for (int j = 0; j < 8; ++j)
            #pragma unroll
            for (int e = 0; e < 4; ++e) acc[mt][j][e] = 0.f;
    float p[4] = {0.f, 0.f, 0.f, 0.f};

    const int G = 8 * 32;

    // prologue: preload 3 stages (groups 0,1,2)
    #pragma unroll
    for (int q = 0; q < STG - 1; ++q) {
        int n0 = (q >> 5) * BN, k0 = (q & 31) * BKg;
        uint32_t base = sb + (q & 3) * STAGE_BYTES;
        cpa16(base + lr * LDT + lc,            Ag + (size_t)lr * Hd + k0 + lck);
        cpa16(base + (lr + 64) * LDT + lc,     Ag + (size_t)(lr + 64) * Hd + k0 + lck);
        cpa16(base + SB_OFF + lr * LDT + lc,        Bg + (size_t)(n0 + lr) * Hd + k0 + lck);
        cpa16(base + SB_OFF + (lr + 64) * LDT + lc, Bg + (size_t)(n0 + lr + 64) * Hd + k0 + lck);
        cpa_commit();
    }

    for (int g = 0; g < G; ++g) {
        CPA_WAIT2();       // group g complete (this thread)
        __syncthreads();   // publish ALL threads' group-g copies; also fences
                           // iter g-1's reads of stage (g+3)&3 before overwrite
        int q = g + STG - 1;
        if (q < G) {
            int n0 = (q >> 5) * BN, k0 = (q & 31) * BKg;
            uint32_t base = sb + (q & 3) * STAGE_BYTES;
            cpa16(base + lr * LDT + lc,            Ag + (size_t)lr * Hd + k0 + lck);
            cpa16(base + (lr + 64) * LDT + lc,     Ag + (size_t)(lr + 64) * Hd + k0 + lck);
            cpa16(base + SB_OFF + lr * LDT + lc,        Bg + (size_t)(n0 + lr) * Hd + k0 + lck);
            cpa16(base + SB_OFF + (lr + 64) * LDT + lc, Bg + (size_t)(n0 + lr + 64) * Hd + k0 + lck);
        }
        cpa_commit();      // unconditional: empty groups at tail keep the
                           // wait_group accounting forcing group g complete

        uint32_t ab = sb + (g & 3) * STAGE_BYTES;

        // staggered ks0/ks1: ks0 MMAs cover ks1's LDSM latency
        uint32_t a0[2][4], b0[4][4], a1[2][4], b1[4][4];
        LDSM4(a0[0], ab + aoff[0]);
        LDSM4(a0[1], ab + aoff[1]);
        #pragma unroll
        for (int jp = 0; jp < 4; ++jp) LDSM4(b0[jp], ab + boff[jp]);
        LDSM4(a1[0], ab + aoff[0] + 32);
        LDSM4(a1[1], ab + aoff[1] + 32);

        #pragma unroll
        for (int mt = 0; mt < 2; ++mt)
            #pragma unroll
            for (int j = 0; j < 8; ++j)
                mma16816(acc[mt][j], a0[mt], b0[j >> 1][(j & 1) * 2],
                         b0[j >> 1][(j & 1) * 2 + 1]);

        #pragma unroll
        for (int jp = 0; jp < 4; ++jp) LDSM4(b1[jp], ab + boff[jp] + 32);

        #pragma unroll
        for (int mt = 0; mt < 2; ++mt)
            #pragma unroll
            for (int j = 0; j < 8; ++j)
                mma16816(acc[mt][j], a1[mt], b1[j >> 1][(j & 1) * 2],
                         b1[j >> 1][(j & 1) * 2 + 1]);

        if ((g & 31) == 31) {
            int nt = g >> 5;
            int nb = nt * BN + warpN * 64 + (lane & 3) * 2;
            #pragma unroll
            for (int mt = 0; mt < 2; ++mt)
                #pragma unroll
                for (int j = 0; j < 8; ++j) {
                    int n0e = nb + j * 8;
                    #pragma unroll
                    for (int e = 0; e < 4; ++e) {
                        int n = n0e + (e & 1);
                        float x = acc[mt][j][e] + c_s[n];
                        p[mt * 2 + (e >> 1)] += v_s[n] * fast_tanh(x);
                        acc[mt][j][e] = 0.f;
                    }
                }
        }
    }

    #pragma unroll
    for (int i = 0; i < 4; ++i) {
        p[i] += __shfl_xor_sync(0xFFFFFFFFu, p[i], 1);
        p[i] += __shfl_xor_sync(0xFFFFFFFFu, p[i], 2);
    }
    if ((lane & 3) == 0) {
        #pragma unroll
        for (int mt = 0; mt < 2; ++mt)
            #pragma unroll
            for (int rh = 0; rh < 2; ++rh) {
                int row = warpM * 32 + mt * 16 + (lane >> 2) + rh * 8;
                sred[row * 2 + warpN] = p[mt * 2 + rh];
            }
    }
    __syncthreads();
    if (tid < BM)
        g_scores[m0 + tid] = sred[tid * 2] + sred[tid * 2 + 1];
}

// ---------------------------------------------------------------------------
__global__ void softmax_kernel() {
    int b = blockIdx.x, tid = threadIdx.x;
    __shared__ float red[256];
    float m = -1e30f;
    for (int s = tid; s < Sd; s += 256)
        m = fmaxf(m, g_scores[b * Sd + s]);
    red[tid] = m;
    __syncthreads();
    for (int o = 128; o > 0; o >>= 1) {
        if (tid < o) red[tid] = fmaxf(red[tid], red[tid + o]);
        __syncthreads();
    }
    float mx = red[0];
    __syncthreads();
    float sum = 0.f;
    for (int s = tid; s < Sd; s += 256) {
        float e = expf(g_scores[b * Sd + s] - mx);
        g_weights[b * Sd + s] = e;
        sum += e;
    }
    red[tid] = sum;
    __syncthreads();
    for (int o = 128; o > 0; o >>= 1) {
        if (tid < o) red[tid] += red[tid + o];
        __syncthreads();
    }
    float inv = 1.0f / red[0];
    for (int s = tid; s < Sd; s += 256)
        g_weights[b * Sd + s] *= inv;
}

__global__ void scale_kernel(const float* __restrict__ X, float* __restrict__ out,
                             int total4) {
    int idx = blockIdx.x * blockDim.x + threadIdx.x;
    int stride = gridDim.x * blockDim.x;
    for (int i = idx; i < total4; i += stride) {
        float w = 1.0f + g_weights[i >> 8];
        float4 t = ((const float4*)X)[i];
        t.x *= w; t.y *= w; t.z *= w; t.w *= w;
        ((float4*)out)[i] = t;
    }
}

// ---------------------------------------------------------------------------
extern "C" void kernel_launch(void* const* d_in, const int* in_sizes, int n_in,
                              void* d_out, int out_size) {
    const float* tok  = (const float*)d_in[0];
    const float* asp  = (const float*)d_in[1];
    const float* W    = (const float*)d_in[2];
    const float* bias = (const float*)d_in[3];
    const float* v    = (const float*)d_in[4];
    float* out = (float*)d_out;

    cudaFuncSetAttribute(gemm_score_mma, cudaFuncAttributeMaxDynamicSharedMemorySize,
                         SMEM_TOTAL);

    convert_x<<<4096, 256>>>((const float4*)tok);
    transpose_w<<<dim3(32, 32), dim3(32, 8)>>>(W);
    cvec_kernel<<<dim3(Bd, Hd / 256), 256>>>(asp, W, bias);
    gemm_score_mma<<<(Bd * Sd) / BM, 256, SMEM_TOTAL>>>(v);
    softmax_kernel<<<Bd, 256>>>();
    scale_kernel<<<8192, 256>>>(tok, out, (Bd * Sd * Hd) / 4);
}